// round 2
// baseline (speedup 1.0000x reference)
#include <cuda_runtime.h>

// Problem shape (fixed by reference setup_inputs)
#define BB 32
#define NN 8
#define LQ 256
#define LD 512
#define DD 768
#define D4 (DD / 4)                      // 192 float4 per feature row
#define LSPLIT 4                          // question L-dim split
#define BPS 8                             // blocks per (b,n) doc slice
#define T2 256                            // threads for k2
#define F4_PER_SLICE (LD * D4)            // 98304 float4 per (b,n)
#define CHUNK (F4_PER_SLICE / BPS)        // 12288 float4 per block
#define ITERS (CHUNK / T2)                // 48 per thread

// Scratch (allocation-free rule: __device__ globals)
__device__ float  g_qpart[BB * LSPLIT * DD];
__device__ double g_acc;

// ---------------------------------------------------------------------------
__global__ void k0_zero() { g_acc = 0.0; }

// ---------------------------------------------------------------------------
// qpart[b][c][d] = sum over 64 L-rows of questions[b, l, d]
// grid (BB, LSPLIT), 256 threads; each thread owns 3 d-columns.
__global__ void k1_qsum(const float* __restrict__ q) {
    const int b = blockIdx.x;
    const int c = blockIdx.y;
    const int t = threadIdx.x;

    const float* base = q + (size_t)b * LQ * DD + (size_t)c * (LQ / LSPLIT) * DD;
    float s0 = 0.f, s1 = 0.f, s2 = 0.f;
#pragma unroll 4
    for (int l = 0; l < LQ / LSPLIT; ++l) {
        const float* row = base + (size_t)l * DD;
        s0 += row[t];
        s1 += row[t + 256];
        s2 += row[t + 512];
    }
    float* out = g_qpart + (size_t)(b * LSPLIT + c) * DD;
    out[t]       = s0;
    out[t + 256] = s1;
    out[t + 512] = s2;
}

// ---------------------------------------------------------------------------
// Stream docs once; acc += sign[b,n] * qsum[b,d] * docs[b,n,l,d]
// is_ans: bool in the reference, widened to int32 by the harness.
__global__ void k2_dot(const float* __restrict__ docs,
                       const int* __restrict__ is_ans) {
    __shared__ float  sq[DD];
    __shared__ double warp_sums[T2 / 32];

    const int slice = blockIdx.x / BPS;   // 0..255  (= b*NN + n)
    const int part  = blockIdx.x % BPS;
    const int b     = slice / NN;
    const int t     = threadIdx.x;

    // Sum the 4 question partials into smem (768 floats; 3 per thread).
    for (int i = t; i < DD; i += T2) {
        float s = 0.f;
#pragma unroll
        for (int c = 0; c < LSPLIT; ++c)
            s += g_qpart[(size_t)(b * LSPLIT + c) * DD + i];
        sq[i] = s;
    }
    __syncthreads();

    const float4* base = (const float4*)docs +
                         (size_t)slice * F4_PER_SLICE + (size_t)part * CHUNK;
    const float4* sq4 = (const float4*)sq;

    float acc = 0.f;
#pragma unroll 8
    for (int k = 0; k < ITERS; ++k) {
        const int fi = k * T2 + t;              // float4 idx within chunk
        const float4 v = base[fi];
        // part*CHUNK is a multiple of D4, so d4 depends on fi only.
        const float4 w = sq4[fi % D4];
        acc += v.x * w.x + v.y * w.y + v.z * w.z + v.w * w.w;
    }

    acc *= (is_ans[slice] != 0) ? -1.f : 1.f;

    // warp reduce (fp32), then cross-warp in double
#pragma unroll
    for (int off = 16; off > 0; off >>= 1)
        acc += __shfl_down_sync(0xFFFFFFFFu, acc, off);

    const int warp = t >> 5;
    if ((t & 31) == 0) warp_sums[warp] = (double)acc;
    __syncthreads();

    if (t == 0) {
        double s = 0.0;
#pragma unroll
        for (int w = 0; w < T2 / 32; ++w) s += warp_sums[w];
        atomicAdd(&g_acc, s);
    }
}

// ---------------------------------------------------------------------------
__global__ void k3_finish(float* __restrict__ out) {
    out[0] = (float)(g_acc * (1.0 / ((double)LQ * (double)LD)));
}

// ---------------------------------------------------------------------------
extern "C" void kernel_launch(void* const* d_in, const int* in_sizes, int n_in,
                              void* d_out, int out_size) {
    const float* questions = (const float*)d_in[0];
    const float* docs      = (const float*)d_in[1];
    const int*   is_ans    = (const int*)d_in[2];
    float*       out       = (float*)d_out;

    k0_zero<<<1, 1>>>();
    {
        dim3 g(BB, LSPLIT);
        k1_qsum<<<g, 256>>>(questions);
    }
    k2_dot<<<BB * NN * BPS, T2>>>(docs, is_ans);
    k3_finish<<<1, 1>>>(out);
}

// round 4
// speedup vs baseline: 1.0022x; 1.0022x over previous
#include <cuda_runtime.h>

// Problem shape (fixed by reference setup_inputs)
#define BB 32
#define NN 8
#define LQ 256
#define LD 512
#define DD 768
#define D4 (DD / 4)                      // 192 float4 per feature row
#define LSPLIT 8                          // question L-dim split
#define LCH (LQ / LSPLIT)                 // 32 rows per k1 block
#define BPS 8                             // blocks per (b,n) doc slice
#define NBLK2 (BB * NN * BPS)             // 2048 k2 blocks
#define T2 256                            // threads for k2
#define F4_PER_SLICE (LD * D4)            // 98304 float4 per (b,n)
#define CHUNK (F4_PER_SLICE / BPS)        // 12288 float4 per block
#define ITERS (CHUNK / T2)                // 48 per thread

// Scratch (allocation-free rule: __device__ globals; zero-initialized at load)
__device__ float4       g_qpart[BB * LSPLIT * D4];
__device__ double       g_acc;
__device__ unsigned int g_count;

// ---------------------------------------------------------------------------
// qpart[b][c][:] = sum over 32 L-rows of questions[b, c*32+l, :]
// grid (BB, LSPLIT), 192 threads; one float4 column per thread.
__global__ void k1_qsum(const float4* __restrict__ q) {
    const int b = blockIdx.x;
    const int c = blockIdx.y;
    const int t = threadIdx.x;           // 0..191

    const float4* base = q + ((size_t)b * LQ + (size_t)c * LCH) * D4 + t;
    float4 s = make_float4(0.f, 0.f, 0.f, 0.f);
#pragma unroll 8
    for (int l = 0; l < LCH; ++l) {
        const float4 v = base[(size_t)l * D4];
        s.x += v.x; s.y += v.y; s.z += v.z; s.w += v.w;
    }
    g_qpart[(size_t)(b * LSPLIT + c) * D4 + t] = s;
}

// ---------------------------------------------------------------------------
// Stream docs once; acc += sign[b,n] * qsum[b,d] * docs[b,n,l,d].
// Last finishing block scales, writes out, and resets scratch for the next
// graph replay (deterministic across calls).
__global__ void k2_dot(const float* __restrict__ docs,
                       const int* __restrict__ is_ans,
                       float* __restrict__ out) {
    __shared__ float4 sq4[D4];
    __shared__ double warp_sums[T2 / 32];

    const int slice = blockIdx.x / BPS;   // 0..255  (= b*NN + n)
    const int part  = blockIdx.x % BPS;
    const int b     = slice / NN;
    const int t     = threadIdx.x;

    // Combine the 8 question partials into smem (192 float4; t<192 each owns 1).
    if (t < D4) {
        float4 s = make_float4(0.f, 0.f, 0.f, 0.f);
#pragma unroll
        for (int c = 0; c < LSPLIT; ++c) {
            const float4 v = g_qpart[(size_t)(b * LSPLIT + c) * D4 + t];
            s.x += v.x; s.y += v.y; s.z += v.z; s.w += v.w;
        }
        sq4[t] = s;
    }
    __syncthreads();

    const float4* base = (const float4*)docs +
                         (size_t)slice * F4_PER_SLICE + (size_t)part * CHUNK;

    float acc = 0.f;
#pragma unroll 8
    for (int k = 0; k < ITERS; ++k) {
        const int fi = k * T2 + t;              // float4 idx within chunk
        const float4 v = base[fi];
        // part*CHUNK is a multiple of D4, so d4 depends on fi only.
        const float4 w = sq4[fi % D4];
        acc += v.x * w.x + v.y * w.y + v.z * w.z + v.w * w.w;
    }

    acc *= (is_ans[slice] != 0) ? -1.f : 1.f;

    // warp reduce (fp32), then cross-warp in double
#pragma unroll
    for (int off = 16; off > 0; off >>= 1)
        acc += __shfl_down_sync(0xFFFFFFFFu, acc, off);

    const int warp = t >> 5;
    if ((t & 31) == 0) warp_sums[warp] = (double)acc;
    __syncthreads();

    if (t == 0) {
        double s = 0.0;
#pragma unroll
        for (int w = 0; w < T2 / 32; ++w) s += warp_sums[w];
        atomicAdd(&g_acc, s);
        __threadfence();
        const unsigned int done = atomicAdd(&g_count, 1u);
        if (done == NBLK2 - 1) {
            // All blocks' g_acc contributions are visible (fence + atomic order).
            const double tot = *((volatile double*)&g_acc);
            out[0] = (float)(tot * (1.0 / ((double)LQ * (double)LD)));
            // Reset scratch for the next graph replay.
            g_acc   = 0.0;
            __threadfence();
            g_count = 0u;
        }
    }
}

// ---------------------------------------------------------------------------
extern "C" void kernel_launch(void* const* d_in, const int* in_sizes, int n_in,
                              void* d_out, int out_size) {
    const float* questions = (const float*)d_in[0];
    const float* docs      = (const float*)d_in[1];
    const int*   is_ans    = (const int*)d_in[2];
    float*       out       = (float*)d_out;

    {
        dim3 g(BB, LSPLIT);
        k1_qsum<<<g, D4>>>((const float4*)questions);
    }
    k2_dot<<<NBLK2, T2>>>(docs, is_ans, out);
}

// round 5
// speedup vs baseline: 1.2105x; 1.2079x over previous
#include <cuda_runtime.h>

// Problem shape (fixed by reference setup_inputs)
#define BB 32
#define NN 8
#define LQ 256
#define LD 512
#define DD 768
#define D4 (DD / 4)                      // 192 float4 per feature row
#define LSPLIT 8                          // question L-dim split (k1)
#define LCH (LQ / LSPLIT)                 // 32 rows per k1 block
#define BPS 4                             // blocks per (b,n) doc slice
#define NBLK2 (BB * NN * BPS)             // 1024 k2 blocks
#define T2 D4                             // 192 threads: one float4 column each
#define ROWS (LD / BPS)                   // 128 doc rows per k2 block
#define F4_PER_SLICE (LD * D4)            // 98304 float4 per (b,n)

// Scratch (allocation-free rule: __device__ globals; zero-initialized at load)
__device__ float4       g_qpart[BB * LSPLIT * D4];
__device__ double       g_acc;
__device__ unsigned int g_count;

// ---------------------------------------------------------------------------
// qpart[b][c][:] = sum over 32 L-rows of questions[b, c*32+l, :]
// grid (BB, LSPLIT), 192 threads; one float4 column per thread.
__global__ void k1_qsum(const float4* __restrict__ q) {
    const int b = blockIdx.x;
    const int c = blockIdx.y;
    const int t = threadIdx.x;           // 0..191

    const float4* base = q + ((size_t)b * LQ + (size_t)c * LCH) * D4 + t;
    float4 s = make_float4(0.f, 0.f, 0.f, 0.f);
#pragma unroll 8
    for (int l = 0; l < LCH; ++l) {
        const float4 v = base[(size_t)l * D4];
        s.x += v.x; s.y += v.y; s.z += v.z; s.w += v.w;
    }
    g_qpart[(size_t)(b * LSPLIT + c) * D4 + t] = s;
}

// ---------------------------------------------------------------------------
// Each thread owns one float4 d-column; streams ROWS rows summing its column
// (pure LDG.128 + FADD), then dots the column-sum with qsum once at the end.
// Last finishing block scales, writes out, resets scratch (graph-replayable).
__global__ void __launch_bounds__(T2) k2_dot(const float* __restrict__ docs,
                                             const int* __restrict__ is_ans,
                                             float* __restrict__ out) {
    __shared__ double warp_sums[T2 / 32];

    const int slice = blockIdx.x / BPS;   // 0..255  (= b*NN + n)
    const int part  = blockIdx.x % BPS;
    const int b     = slice / NN;
    const int t     = threadIdx.x;        // 0..191 = float4 column

    const float4* base = (const float4*)docs +
                         (size_t)slice * F4_PER_SLICE +
                         (size_t)part * ROWS * D4 + t;

    // Column sum over ROWS rows (weight-free streaming loop).
    float4 cs = make_float4(0.f, 0.f, 0.f, 0.f);
#pragma unroll 8
    for (int l = 0; l < ROWS; ++l) {
        const float4 v = base[(size_t)l * D4];
        cs.x += v.x; cs.y += v.y; cs.z += v.z; cs.w += v.w;
    }

    // Gather this column's q-weight (sum of the 8 partials) and dot.
    float4 w = make_float4(0.f, 0.f, 0.f, 0.f);
#pragma unroll
    for (int c = 0; c < LSPLIT; ++c) {
        const float4 v = g_qpart[(size_t)(b * LSPLIT + c) * D4 + t];
        w.x += v.x; w.y += v.y; w.z += v.z; w.w += v.w;
    }
    float acc = cs.x * w.x + cs.y * w.y + cs.z * w.z + cs.w * w.w;
    acc *= (is_ans[slice] != 0) ? -1.f : 1.f;

    // Warp reduce (fp32), then cross-warp in double.
#pragma unroll
    for (int off = 16; off > 0; off >>= 1)
        acc += __shfl_down_sync(0xFFFFFFFFu, acc, off);

    const int warp = t >> 5;
    if ((t & 31) == 0) warp_sums[warp] = (double)acc;
    __syncthreads();

    if (t == 0) {
        double s = 0.0;
#pragma unroll
        for (int w2 = 0; w2 < T2 / 32; ++w2) s += warp_sums[w2];
        atomicAdd(&g_acc, s);
        __threadfence();
        const unsigned int done = atomicAdd(&g_count, 1u);
        if (done == NBLK2 - 1) {
            const double tot = *((volatile double*)&g_acc);
            out[0] = (float)(tot * (1.0 / ((double)LQ * (double)LD)));
            // Reset scratch for the next graph replay.
            g_acc   = 0.0;
            __threadfence();
            g_count = 0u;
        }
    }
}

// ---------------------------------------------------------------------------
extern "C" void kernel_launch(void* const* d_in, const int* in_sizes, int n_in,
                              void* d_out, int out_size) {
    const float* questions = (const float*)d_in[0];
    const float* docs      = (const float*)d_in[1];
    const int*   is_ans    = (const int*)d_in[2];
    float*       out       = (float*)d_out;

    {
        dim3 g(BB, LSPLIT);
        k1_qsum<<<g, D4>>>((const float4*)questions);
    }
    k2_dot<<<NBLK2, T2>>>(docs, is_ans, out);
}

// round 7
// speedup vs baseline: 1.3604x; 1.1238x over previous
#include <cuda_runtime.h>

// Problem shape (fixed by reference setup_inputs)
#define BB 32
#define NN 8
#define LQ 256
#define LD 512
#define DD 768
#define D4 (DD / 4)                      // 192 float4 per feature row
#define LSPLIT 8                          // question L-dim split
#define LCH (LQ / LSPLIT)                 // 32 q-rows per q-block
#define QBLK (BB * LSPLIT)                // 256 question blocks
#define BPS 4                             // doc blocks per (b,n) slice
#define NBLK2 (BB * NN * BPS)             // 1024 doc blocks
#define TT D4                             // 192 threads: one float4 column each
#define ROWS (LD / BPS)                   // 128 doc rows per doc block
#define F4_PER_SLICE (LD * D4)            // 98304 float4 per (b,n)

// Scratch (allocation-free rule: __device__ globals; zero-initialized at load)
__device__ float4       g_qpart[BB * LSPLIT * D4];
__device__ double       g_acc;
__device__ unsigned int g_count;   // doc-block completion counter
__device__ unsigned int g_qcount;  // question-block completion counter

// ---------------------------------------------------------------------------
// Single fused kernel.
//  blocks [0, QBLK):       question partial sums -> g_qpart, bump g_qcount.
//  blocks [QBLK, +NBLK2):  stream a doc chunk (column sums, weight-free),
//                          then wait for g_qcount==QBLK (already done by then),
//                          dot with qsum, reduce, atomic into g_acc.
//  Last doc block writes out and resets scratch (graph-replay safe).
__global__ void __launch_bounds__(TT) fused(const float4* __restrict__ q,
                                            const float*  __restrict__ docs,
                                            const int*    __restrict__ is_ans,
                                            float*        __restrict__ out) {
    const int t = threadIdx.x;            // 0..191 = float4 column

    // ---------------- question blocks ----------------
    if (blockIdx.x < QBLK) {
        const int b = blockIdx.x / LSPLIT;
        const int c = blockIdx.x % LSPLIT;
        const float4* base = q + ((size_t)b * LQ + (size_t)c * LCH) * D4 + t;
        float4 s = make_float4(0.f, 0.f, 0.f, 0.f);
#pragma unroll 8
        for (int l = 0; l < LCH; ++l) {
            const float4 v = base[(size_t)l * D4];
            s.x += v.x; s.y += v.y; s.z += v.z; s.w += v.w;
        }
        g_qpart[(size_t)blockIdx.x * D4 + t] = s;
        __threadfence();
        __syncthreads();
        if (t == 0) atomicAdd(&g_qcount, 1u);
        return;
    }

    // ---------------- doc blocks ----------------
    __shared__ double warp_sums[TT / 32];

    const int db    = blockIdx.x - QBLK;  // 0..1023
    const int slice = db / BPS;           // 0..255  (= b*NN + n)
    const int part  = db % BPS;
    const int b     = slice / NN;

    const float4* base = (const float4*)docs +
                         (size_t)slice * F4_PER_SLICE +
                         (size_t)part * ROWS * D4 + t;

    // Column sum over ROWS rows: pure streaming (evict-first loads).
    float4 cs = make_float4(0.f, 0.f, 0.f, 0.f);
#pragma unroll 8
    for (int l = 0; l < ROWS; ++l) {
        const float4 v = __ldcs(base + (size_t)l * D4);
        cs.x += v.x; cs.y += v.y; cs.z += v.z; cs.w += v.w;
    }

    // Wait for question partials (normally already complete — no real spin).
    if (t == 0) {
        while (atomicAdd(&g_qcount, 0u) < QBLK) { }
    }
    __syncthreads();
    __threadfence();  // acquire: make g_qpart writes visible to all threads

    // Gather this column's q-weight (sum of the 8 partials) and dot.
    float4 w = make_float4(0.f, 0.f, 0.f, 0.f);
#pragma unroll
    for (int c = 0; c < LSPLIT; ++c) {
        const float4 v = g_qpart[(size_t)(b * LSPLIT + c) * D4 + t];
        w.x += v.x; w.y += v.y; w.z += v.z; w.w += v.w;
    }
    float acc = cs.x * w.x + cs.y * w.y + cs.z * w.z + cs.w * w.w;
    acc *= (is_ans[slice] != 0) ? -1.f : 1.f;

    // Warp reduce (fp32), then cross-warp in double.
#pragma unroll
    for (int off = 16; off > 0; off >>= 1)
        acc += __shfl_down_sync(0xFFFFFFFFu, acc, off);

    const int warp = t >> 5;
    if ((t & 31) == 0) warp_sums[warp] = (double)acc;
    __syncthreads();

    if (t == 0) {
        double s = 0.0;
#pragma unroll
        for (int w2 = 0; w2 < TT / 32; ++w2) s += warp_sums[w2];
        atomicAdd(&g_acc, s);
        __threadfence();
        const unsigned int done = atomicAdd(&g_count, 1u);
        if (done == NBLK2 - 1) {
            const double tot = *((volatile double*)&g_acc);
            out[0] = (float)(tot * (1.0 / ((double)LQ * (double)LD)));
            // Reset scratch for the next graph replay.
            g_acc   = 0.0;
            g_qcount = 0u;
            __threadfence();
            g_count = 0u;
        }
    }
}

// ---------------------------------------------------------------------------
extern "C" void kernel_launch(void* const* d_in, const int* in_sizes, int n_in,
                              void* d_out, int out_size) {
    const float* questions = (const float*)d_in[0];
    const float* docs      = (const float*)d_in[1];
    const int*   is_ans    = (const int*)d_in[2];
    float*       out       = (float*)d_out;

    fused<<<QBLK + NBLK2, TT>>>((const float4*)questions, docs, is_ans, out);
}